// round 2
// baseline (speedup 1.0000x reference)
#include <cuda_runtime.h>
#include <cuda_bf16.h>

// Problem dims (fixed by the dataset)
#define B_  8
#define S_  1024
#define D_  1024
#define R_  256

#define BM 128
#define BN 128
#define BK 16
#define TM 8
#define TN 8

// Scratch for factored intermediates (8 MB each) — __device__ globals per alloc rules.
__device__ float g_left [(size_t)B_ * S_ * R_];
__device__ float g_right[(size_t)B_ * S_ * R_];

// ---------------------------------------------------------------------------
// NN GEMM: C[M,N] = A[M,K] @ B[K,N], all row-major. Exact tiling (no bounds).
// ---------------------------------------------------------------------------
__global__ __launch_bounds__(256) void gemm_nn(
    const float* __restrict__ A, const float* __restrict__ Bm,
    float* __restrict__ C, int M, int N, int K)
{
    __shared__ float As[BK][BM];
    __shared__ float Bs[BK][BN];

    const int tid  = threadIdx.x;
    const int row0 = blockIdx.y * BM;
    const int col0 = blockIdx.x * BN;
    const int tx = tid & 15;
    const int ty = tid >> 4;

    float acc[TM][TN];
#pragma unroll
    for (int i = 0; i < TM; i++)
#pragma unroll
        for (int j = 0; j < TN; j++) acc[i][j] = 0.f;

    for (int kt = 0; kt < K; kt += BK) {
        // Load A tile 128x16 (transposed into As[k][m])
#pragma unroll
        for (int it = 0; it < 2; it++) {
            int idx  = tid + it * 256;      // 512 float4 total
            int ar   = idx >> 2;            // row within tile
            int ac4  = idx & 3;             // which float4 along K
            float4 v = *(const float4*)&A[(size_t)(row0 + ar) * K + kt + ac4 * 4];
            As[ac4 * 4 + 0][ar] = v.x;
            As[ac4 * 4 + 1][ar] = v.y;
            As[ac4 * 4 + 2][ar] = v.z;
            As[ac4 * 4 + 3][ar] = v.w;
        }
        // Load B tile 16x128 (direct, coalesced)
#pragma unroll
        for (int it = 0; it < 2; it++) {
            int idx = tid + it * 256;
            int br  = idx >> 5;             // k row (16 rows x 32 float4)
            int bc4 = idx & 31;
            *(float4*)&Bs[br][bc4 * 4] =
                *(const float4*)&Bm[(size_t)(kt + br) * N + col0 + bc4 * 4];
        }
        __syncthreads();

#pragma unroll
        for (int k = 0; k < BK; k++) {
            float a[TM], b[TN];
            *(float4*)&a[0] = *(const float4*)&As[k][ty * TM];
            *(float4*)&a[4] = *(const float4*)&As[k][ty * TM + 4];
            *(float4*)&b[0] = *(const float4*)&Bs[k][tx * TN];
            *(float4*)&b[4] = *(const float4*)&Bs[k][tx * TN + 4];
#pragma unroll
            for (int i = 0; i < TM; i++)
#pragma unroll
                for (int j = 0; j < TN; j++)
                    acc[i][j] = fmaf(a[i], b[j], acc[i][j]);
        }
        __syncthreads();
    }

#pragma unroll
    for (int i = 0; i < TM; i++) {
        float* crow = &C[(size_t)(row0 + ty * TM + i) * N + col0 + tx * TN];
        *(float4*)&crow[0] = *(float4*)&acc[i][0];
        *(float4*)&crow[4] = *(float4*)&acc[i][4];
    }
}

// ---------------------------------------------------------------------------
// NT GEMM (+ optional bias, batched via blockIdx.z):
//   C[z][M,N] = A[z][M,K] @ B[z][N,K]^T  (+ bias[0])
// Both operands K-contiguous. Exact tiling.
// ---------------------------------------------------------------------------
__global__ __launch_bounds__(256) void gemm_nt(
    const float* __restrict__ A, const float* __restrict__ Bm,
    float* __restrict__ C, int M, int N, int K,
    size_t strideA, size_t strideB, size_t strideC,
    const float* __restrict__ bias)
{
    __shared__ float As[BK][BM];
    __shared__ float Bs[BK][BN];

    const int z = blockIdx.z;
    A  += (size_t)z * strideA;
    Bm += (size_t)z * strideB;
    C  += (size_t)z * strideC;

    const int tid  = threadIdx.x;
    const int row0 = blockIdx.y * BM;
    const int col0 = blockIdx.x * BN;
    const int tx = tid & 15;
    const int ty = tid >> 4;

    float acc[TM][TN];
#pragma unroll
    for (int i = 0; i < TM; i++)
#pragma unroll
        for (int j = 0; j < TN; j++) acc[i][j] = 0.f;

    for (int kt = 0; kt < K; kt += BK) {
#pragma unroll
        for (int it = 0; it < 2; it++) {
            int idx  = tid + it * 256;
            int ar   = idx >> 2;
            int ac4  = idx & 3;
            float4 v = *(const float4*)&A[(size_t)(row0 + ar) * K + kt + ac4 * 4];
            As[ac4 * 4 + 0][ar] = v.x;
            As[ac4 * 4 + 1][ar] = v.y;
            As[ac4 * 4 + 2][ar] = v.z;
            As[ac4 * 4 + 3][ar] = v.w;
        }
#pragma unroll
        for (int it = 0; it < 2; it++) {
            int idx  = tid + it * 256;
            int br   = idx >> 2;            // n within tile
            int bc4  = idx & 3;             // k/4
            float4 v = *(const float4*)&Bm[(size_t)(col0 + br) * K + kt + bc4 * 4];
            Bs[bc4 * 4 + 0][br] = v.x;
            Bs[bc4 * 4 + 1][br] = v.y;
            Bs[bc4 * 4 + 2][br] = v.z;
            Bs[bc4 * 4 + 3][br] = v.w;
        }
        __syncthreads();

#pragma unroll
        for (int k = 0; k < BK; k++) {
            float a[TM], b[TN];
            *(float4*)&a[0] = *(const float4*)&As[k][ty * TM];
            *(float4*)&a[4] = *(const float4*)&As[k][ty * TM + 4];
            *(float4*)&b[0] = *(const float4*)&Bs[k][tx * TN];
            *(float4*)&b[4] = *(const float4*)&Bs[k][tx * TN + 4];
#pragma unroll
            for (int i = 0; i < TM; i++)
#pragma unroll
                for (int j = 0; j < TN; j++)
                    acc[i][j] = fmaf(a[i], b[j], acc[i][j]);
        }
        __syncthreads();
    }

    const float bv = bias ? bias[0] : 0.f;
#pragma unroll
    for (int i = 0; i < TM; i++) {
        float* crow = &C[(size_t)(row0 + ty * TM + i) * N + col0 + tx * TN];
        float4 lo = make_float4(acc[i][0] + bv, acc[i][1] + bv, acc[i][2] + bv, acc[i][3] + bv);
        float4 hi = make_float4(acc[i][4] + bv, acc[i][5] + bv, acc[i][6] + bv, acc[i][7] + bv);
        *(float4*)&crow[0] = lo;
        *(float4*)&crow[4] = hi;
    }
}

extern "C" void kernel_launch(void* const* d_in, const int* in_sizes, int n_in,
                              void* d_out, int out_size)
{
    const float* batch  = (const float*)d_in[0];   // (B,S,D)
    const float* proj_L = (const float*)d_in[1];   // (D,R)
    const float* proj_R = (const float*)d_in[2];   // (R,D)
    const float* bias   = (const float*)d_in[3];   // (1,)
    float* out = (float*)d_out;                    // (B,S,S)

    float* left;
    float* right;
    cudaGetSymbolAddress((void**)&left,  g_left);
    cudaGetSymbolAddress((void**)&right, g_right);

    const int M = B_ * S_;   // 8192

    // left = batch @ proj_L   (M x R_, K = D_)   NN
    {
        dim3 grid(R_ / BN, M / BM, 1);
        gemm_nn<<<grid, 256>>>(batch, proj_L, left, M, R_, D_);
    }
    // right = batch @ proj_R^T  (M x R_, K = D_)  NT
    {
        dim3 grid(R_ / BN, M / BM, 1);
        gemm_nt<<<grid, 256>>>(batch, proj_R, right, M, R_, D_,
                               0, 0, 0, nullptr);
    }
    // logits[b] = left[b] @ right[b]^T + bias   (S x S, K = R_)  batched NT
    {
        dim3 grid(S_ / BN, S_ / BM, B_);
        gemm_nt<<<grid, 256>>>(left, right, out, S_, S_, R_,
                               (size_t)S_ * R_, (size_t)S_ * R_, (size_t)S_ * S_,
                               bias);
    }
}

// round 4
// speedup vs baseline: 3.6260x; 3.6260x over previous
#include <cuda_runtime.h>
#include <cuda_bf16.h>
#include <cstdint>

// tcgen05 is arch-SPECIFIC (sm_103a): guard device code so the harness's plain
// compute_103 PTX pass compiles. The sm_103a cubin is what actually runs.
#if defined(__CUDA_ARCH__) && (defined(__CUDA_ARCH_FEAT_SM103_ALL) || \
    defined(__CUDA_ARCH_FEAT_SM100_ALL) || defined(__CUDA_ARCH_SPECIFIC__) || \
    defined(__CUDA_ARCH_FAMILY_SPECIFIC__))
#define HAS_TCGEN05 1
#else
#define HAS_TCGEN05 0
#endif

// Problem dims (fixed)
#define B_  8
#define S_  1024
#define D_  1024
#define R_  256

#define TILE_M 128
#define TILE_N 128
#define KCH    64          // bf16 elements per K-chunk (=128B SW128 row)
#define STAGES 3
#define STAGE_BYTES 32768  // 16KB A + 16KB B
#define SMEM_DYN (1024 + STAGES*STAGE_BYTES + 256)

// ---------------- scratch (device globals; no allocs allowed) ----------------
__device__ __nv_bfloat16 g_batch_hi[(size_t)B_*S_*D_];
__device__ __nv_bfloat16 g_batch_lo[(size_t)B_*S_*D_];
__device__ __nv_bfloat16 g_LT_hi[(size_t)R_*D_];   // proj_L transposed (R,D)
__device__ __nv_bfloat16 g_LT_lo[(size_t)R_*D_];
__device__ __nv_bfloat16 g_PR_hi[(size_t)R_*D_];   // proj_R (R,D)
__device__ __nv_bfloat16 g_PR_lo[(size_t)R_*D_];
__device__ __nv_bfloat16 g_left_hi[(size_t)B_*S_*R_];
__device__ __nv_bfloat16 g_left_lo[(size_t)B_*S_*R_];
__device__ __nv_bfloat16 g_right_hi[(size_t)B_*S_*R_];
__device__ __nv_bfloat16 g_right_lo[(size_t)B_*S_*R_];

// ---------------- PTX helpers ----------------
__device__ __forceinline__ uint32_t smem_u32(const void* p) {
    uint32_t a;
    asm("{ .reg .u64 t; cvta.to.shared.u64 t, %1; cvt.u32.u64 %0, t; }" : "=r"(a) : "l"(p));
    return a;
}
#define SW128(off) ((off) ^ (((off) >> 3) & 0x70))

__device__ __forceinline__ void cp_async16(uint32_t sdst, const void* gsrc) {
    asm volatile("cp.async.cg.shared.global [%0], [%1], 16;" :: "r"(sdst), "l"(gsrc) : "memory");
}
#define CP_COMMIT() asm volatile("cp.async.commit_group;" ::: "memory")
#define CP_WAIT2()  asm volatile("cp.async.wait_group 2;" ::: "memory")

__device__ __forceinline__ void mbar_init(uint32_t a, uint32_t cnt) {
    asm volatile("mbarrier.init.shared.b64 [%0], %1;" :: "r"(a), "r"(cnt) : "memory");
}
__device__ __forceinline__ void mbar_wait(uint32_t a, uint32_t parity) {
    asm volatile(
        "{\n\t.reg .pred P;\n\t"
        "WL_%=:\n\t"
        "mbarrier.try_wait.parity.acquire.cta.shared::cta.b64 P, [%0], %1, 0x989680;\n\t"
        "@P bra WD_%=;\n\t"
        "bra WL_%=;\n\t"
        "WD_%=:\n\t}"
        :: "r"(a), "r"(parity) : "memory");
}

#if HAS_TCGEN05
__device__ __forceinline__ uint32_t elect_one() {
    uint32_t p;
    asm volatile("{ .reg .pred p; elect.sync _|p, 0xFFFFFFFF; selp.b32 %0,1,0,p; }" : "=r"(p));
    return p;
}

// SW128 K-major SMEM descriptor (layout=2, version=1, SBO=64, LBO=1)
__device__ __forceinline__ uint64_t make_desc(uint32_t addr) {
    const uint64_t base = (uint64_t(2) << 61) | (uint64_t(1) << 46)
                        | (uint64_t(64) << 32) | (uint64_t(1) << 16);
    return base | ((uint64_t)(addr >> 4) & 0x3FFF);
}

// bf16 SS MMA, cta_group::1, kind::f16, M=128 N=128, fp32 accum
#define IDESC_128x128 ((1u<<4) | (1u<<7) | (1u<<10) | ((TILE_N/8)<<17) | ((TILE_M/16)<<24))

__device__ __forceinline__ void mma_bf16_ss(uint32_t d, uint64_t ad, uint64_t bd,
                                            uint32_t idesc, bool acc) {
    uint32_t en = acc ? 1u : 0u, z = 0u;
    asm volatile(
        "{\n\t.reg .pred p;\n\tsetp.ne.u32 p, %5, 0;\n\t"
        "tcgen05.mma.cta_group::1.kind::f16 [%0], %1, %2, %3, {%4,%4,%4,%4}, p;\n\t}"
        :: "r"(d), "l"(ad), "l"(bd), "r"(idesc), "r"(z), "r"(en) : "memory");
}
__device__ __forceinline__ void tc_commit(uint32_t mbar) {
    asm volatile(
        "tcgen05.commit.cta_group::1.mbarrier::arrive::one.shared::cluster.b64 [%0];"
        :: "r"(mbar) : "memory");
}
#endif  // HAS_TCGEN05

// ---------------- conversion kernels ----------------
__device__ __forceinline__ void split1(float v, __nv_bfloat16& h, __nv_bfloat16& l) {
    h = __float2bfloat16_rn(v);
    l = __float2bfloat16_rn(v - __bfloat162float(h));
}

__global__ void split_kernel(const float4* __restrict__ src,
                             __nv_bfloat16* __restrict__ hi,
                             __nv_bfloat16* __restrict__ lo) {
    int i = blockIdx.x * blockDim.x + threadIdx.x;
    float4 v = src[i];
    __nv_bfloat16 h[4], l[4];
    split1(v.x, h[0], l[0]); split1(v.y, h[1], l[1]);
    split1(v.z, h[2], l[2]); split1(v.w, h[3], l[3]);
    *(uint64_t*)(hi + (size_t)i * 4) = *(const uint64_t*)h;
    *(uint64_t*)(lo + (size_t)i * 4) = *(const uint64_t*)l;
}

// proj_L (D,R) -> transposed split (R,D)
__global__ void tsplit_kernel(const float* __restrict__ src,
                              __nv_bfloat16* __restrict__ hi,
                              __nv_bfloat16* __restrict__ lo) {
    __shared__ float t[32][33];
    int tx = threadIdx.x, ty = threadIdx.y;
    int d0 = blockIdx.y * 32, r0 = blockIdx.x * 32;
    t[ty][tx] = src[(size_t)(d0 + ty) * R_ + r0 + tx];
    __syncthreads();
    float v = t[tx][ty];                // out[r0+ty][d0+tx]
    size_t o = (size_t)(r0 + ty) * D_ + d0 + tx;
    __nv_bfloat16 h, l; split1(v, h, l);
    hi[o] = h; lo[o] = l;
}

// ---------------- tcgen05 NT GEMM with 3-term bf16 split ----------------
// C[M,N] = sum_p A_p[M,K] * B_p[N,K]^T  over pairs (hi,hi),(hi,lo),(lo,hi)
// out: fp32 (+bias) if Cf != null, else bf16 hi/lo split.
__global__ void __launch_bounds__(256)
tc_gemm(const __nv_bfloat16* __restrict__ A_hi, const __nv_bfloat16* __restrict__ A_lo,
        const __nv_bfloat16* __restrict__ B_hi, const __nv_bfloat16* __restrict__ B_lo,
        float* __restrict__ Cf,
        __nv_bfloat16* __restrict__ Chi, __nv_bfloat16* __restrict__ Clo,
        const float* __restrict__ bias,
        int K, int ldc,
        long strideA, long strideB, long strideC)
{
#if HAS_TCGEN05
    extern __shared__ char smem_raw[];
    const uint32_t raw = smem_u32(smem_raw);
    const uint32_t tileBase = (raw + 1023u) & ~1023u;
    const uint32_t barBase  = tileBase + STAGES * STAGE_BYTES;
    const uint32_t tmemSlot = barBase + 64;

    const int tid = threadIdx.x, wid = tid >> 5, lane = tid & 31;
    const int z  = blockIdx.z;
    const int m0 = blockIdx.y * TILE_M;
    const int n0 = blockIdx.x * TILE_N;

    A_hi += (size_t)z * strideA;  A_lo += (size_t)z * strideA;
    B_hi += (size_t)z * strideB;  B_lo += (size_t)z * strideB;

    const int kch    = K / KCH;
    const int chunks = 3 * kch;

    if (wid == 0) {
        asm volatile("tcgen05.alloc.cta_group::1.sync.aligned.shared::cta.b32 [%0], 128;"
                     :: "r"(tmemSlot) : "memory");
        asm volatile("tcgen05.relinquish_alloc_permit.cta_group::1.sync.aligned;");
    }
    if (tid == 0) {
        mbar_init(barBase + 0, 1);
        mbar_init(barBase + 8, 1);
        mbar_init(barBase + 16, 1);
    }
    __syncthreads();
    uint32_t tmem;
    asm volatile("ld.shared.b32 %0, [%1];" : "=r"(tmem) : "r"(tmemSlot));

    // chunk loader: chunk id -> (pair p, k-chunk kc)
    auto load_chunk = [&](int c, int s) {
        int p  = c / kch;
        int kc = c % kch;
        const __nv_bfloat16* Ap = (p == 2) ? A_lo : A_hi;
        const __nv_bfloat16* Bp = (p == 1) ? B_lo : B_hi;
        const __nv_bfloat16* ab = Ap + (size_t)m0 * K + kc * KCH;
        const __nv_bfloat16* bb = Bp + (size_t)n0 * K + kc * KCH;
        uint32_t sA = tileBase + s * STAGE_BYTES;
        uint32_t sB = sA + 16384;
#pragma unroll
        for (int i = 0; i < 4; i++) {
            int l = tid + i * 256;
            int row = l >> 3, c16 = l & 7;
            cp_async16(sA + SW128(row * 128 + c16 * 16), ab + (size_t)row * K + c16 * 8);
        }
#pragma unroll
        for (int i = 0; i < 4; i++) {
            int l = tid + i * 256;
            int row = l >> 3, c16 = l & 7;
            cp_async16(sB + SW128(row * 128 + c16 * 16), bb + (size_t)row * K + c16 * 8);
        }
    };

    // prologue: stages 0,1
    load_chunk(0, 0); CP_COMMIT();
    load_chunk(1, 1); CP_COMMIT();

    for (int c = 0; c < chunks; c++) {
        int cl = c + STAGES - 1;
        if (cl < chunks) {
            int s = cl % STAGES, u = cl / STAGES;
            if (u > 0) mbar_wait(barBase + s * 8, (u - 1) & 1);
            load_chunk(cl, s);
        }
        CP_COMMIT();
        CP_WAIT2();
        asm volatile("fence.proxy.async.shared::cta;" ::: "memory");
        __syncthreads();
        if (wid == 0) {
            if (elect_one()) {
                int s = c % STAGES;
                uint64_t ad = make_desc(tileBase + s * STAGE_BYTES);
                uint64_t bd = make_desc(tileBase + s * STAGE_BYTES + 16384);
#pragma unroll
                for (int km = 0; km < 4; km++) {  // 4 x K16 = one 64-chunk
                    mma_bf16_ss(tmem, ad + km * 2, bd + km * 2, IDESC_128x128,
                                !(c == 0 && km == 0));
                }
                tc_commit(barBase + s * 8);
            }
        }
    }

    // wait for last chunk's MMA
    {
        int sl = (chunks - 1) % STAGES, ul = (chunks - 1) / STAGES;
        mbar_wait(barBase + sl * 8, ul & 1);
    }
    asm volatile("tcgen05.fence::after_thread_sync;" ::: "memory");

    if (wid < 4) {
        const float bv = bias ? bias[0] : 0.f;
        const int row = m0 + wid * 32 + lane;
#pragma unroll
        for (int pass = 0; pass < 4; pass++) {
            uint32_t r[32];
            asm volatile(
                "tcgen05.ld.sync.aligned.32x32b.x32.b32 "
                "{%0,%1,%2,%3,%4,%5,%6,%7,%8,%9,%10,%11,%12,%13,%14,%15,"
                "%16,%17,%18,%19,%20,%21,%22,%23,%24,%25,%26,%27,%28,%29,%30,%31}, [%32];"
                : "=r"(r[0]), "=r"(r[1]), "=r"(r[2]), "=r"(r[3]), "=r"(r[4]), "=r"(r[5]),
                  "=r"(r[6]), "=r"(r[7]), "=r"(r[8]), "=r"(r[9]), "=r"(r[10]), "=r"(r[11]),
                  "=r"(r[12]), "=r"(r[13]), "=r"(r[14]), "=r"(r[15]), "=r"(r[16]), "=r"(r[17]),
                  "=r"(r[18]), "=r"(r[19]), "=r"(r[20]), "=r"(r[21]), "=r"(r[22]), "=r"(r[23]),
                  "=r"(r[24]), "=r"(r[25]), "=r"(r[26]), "=r"(r[27]), "=r"(r[28]), "=r"(r[29]),
                  "=r"(r[30]), "=r"(r[31])
                : "r"(tmem + pass * 32));
            asm volatile("tcgen05.wait::ld.sync.aligned;" ::: "memory");

            if (Cf) {
                float* dst = Cf + (size_t)z * strideC + (size_t)row * ldc + n0 + pass * 32;
#pragma unroll
                for (int g = 0; g < 8; g++) {
                    float4 v = make_float4(__uint_as_float(r[g*4+0]) + bv,
                                           __uint_as_float(r[g*4+1]) + bv,
                                           __uint_as_float(r[g*4+2]) + bv,
                                           __uint_as_float(r[g*4+3]) + bv);
                    *(float4*)(dst + g * 4) = v;
                }
            } else {
                size_t o = (size_t)row * ldc + n0 + pass * 32;
#pragma unroll
                for (int g = 0; g < 4; g++) {
                    union { __nv_bfloat16 h[8]; uint4 u; } ph, pl;
#pragma unroll
                    for (int e = 0; e < 8; e++) {
                        float v = __uint_as_float(r[g * 8 + e]);
                        split1(v, ph.h[e], pl.h[e]);
                    }
                    *(uint4*)(Chi + o + g * 8) = ph.u;
                    *(uint4*)(Clo + o + g * 8) = pl.u;
                }
            }
        }
    }
    asm volatile("tcgen05.fence::before_thread_sync;" ::: "memory");
    __syncthreads();
    if (wid == 0) {
        asm volatile("tcgen05.dealloc.cta_group::1.sync.aligned.b32 %0, 128;"
                     :: "r"(tmem) : "memory");
    }
#endif  // HAS_TCGEN05
}

// ---------------- launch ----------------
extern "C" void kernel_launch(void* const* d_in, const int* in_sizes, int n_in,
                              void* d_out, int out_size)
{
    const float* batch  = (const float*)d_in[0];   // (B,S,D)
    const float* proj_L = (const float*)d_in[1];   // (D,R)
    const float* proj_R = (const float*)d_in[2];   // (R,D)
    const float* bias   = (const float*)d_in[3];   // (1,)
    float* out = (float*)d_out;                    // (B,S,S)

    __nv_bfloat16 *batch_hi, *batch_lo, *LT_hi, *LT_lo, *PR_hi, *PR_lo;
    __nv_bfloat16 *left_hi, *left_lo, *right_hi, *right_lo;
    cudaGetSymbolAddress((void**)&batch_hi, g_batch_hi);
    cudaGetSymbolAddress((void**)&batch_lo, g_batch_lo);
    cudaGetSymbolAddress((void**)&LT_hi, g_LT_hi);
    cudaGetSymbolAddress((void**)&LT_lo, g_LT_lo);
    cudaGetSymbolAddress((void**)&PR_hi, g_PR_hi);
    cudaGetSymbolAddress((void**)&PR_lo, g_PR_lo);
    cudaGetSymbolAddress((void**)&left_hi, g_left_hi);
    cudaGetSymbolAddress((void**)&left_lo, g_left_lo);
    cudaGetSymbolAddress((void**)&right_hi, g_right_hi);
    cudaGetSymbolAddress((void**)&right_lo, g_right_lo);

    cudaFuncSetAttribute(tc_gemm, cudaFuncAttributeMaxDynamicSharedMemorySize, SMEM_DYN);

    // 1) input conversions
    split_kernel<<<(B_*S_*D_/4)/256, 256>>>((const float4*)batch, batch_hi, batch_lo);
    split_kernel<<<(R_*D_/4)/256, 256>>>((const float4*)proj_R, PR_hi, PR_lo);
    tsplit_kernel<<<dim3(R_/32, D_/32), dim3(32, 32)>>>(proj_L, LT_hi, LT_lo);

    // 2) left = batch @ proj_L  (M=8192, N=256, K=1024), emit bf16 split
    tc_gemm<<<dim3(R_/TILE_N, (B_*S_)/TILE_M, 1), 256, SMEM_DYN>>>(
        batch_hi, batch_lo, LT_hi, LT_lo,
        nullptr, left_hi, left_lo, nullptr,
        D_, R_, 0, 0, 0);

    // 3) right = batch @ proj_R^T (same shape), emit bf16 split
    tc_gemm<<<dim3(R_/TILE_N, (B_*S_)/TILE_M, 1), 256, SMEM_DYN>>>(
        batch_hi, batch_lo, PR_hi, PR_lo,
        nullptr, right_hi, right_lo, nullptr,
        D_, R_, 0, 0, 0);

    // 4) logits[b] = left[b] @ right[b]^T + bias  (batched, M=N=1024, K=256)
    tc_gemm<<<dim3(S_/TILE_N, S_/TILE_M, B_), 256, SMEM_DYN>>>(
        left_hi, left_lo, right_hi, right_lo,
        out, nullptr, nullptr, bias,
        R_, S_, (long)S_*R_, (long)S_*R_, (long)S_*S_);
}

// round 6
// speedup vs baseline: 4.6663x; 1.2869x over previous
#include <cuda_runtime.h>
#include <cuda_bf16.h>
#include <cstdint>

// tcgen05 is arch-SPECIFIC (sm_103a): guard device code so the harness's plain
// compute_103 PTX pass compiles. The sm_103a cubin is what actually runs.
#if defined(__CUDA_ARCH__) && (defined(__CUDA_ARCH_FEAT_SM103_ALL) || \
    defined(__CUDA_ARCH_FEAT_SM100_ALL) || defined(__CUDA_ARCH_SPECIFIC__) || \
    defined(__CUDA_ARCH_FAMILY_SPECIFIC__))
#define HAS_TCGEN05 1
#else
#define HAS_TCGEN05 0
#endif

// Problem dims (fixed)
#define B_  8
#define S_  1024
#define D_  1024
#define R_  256

#define TILE_M 128
#define KCH    64          // bf16 K elements per chunk (=128B SW128 row)

// ---------------- scratch (device globals; no allocs allowed) ----------------
__device__ __nv_bfloat16 g_batch_hi[(size_t)B_*S_*D_];
__device__ __nv_bfloat16 g_batch_lo[(size_t)B_*S_*D_];
__device__ __nv_bfloat16 g_LT_hi[(size_t)R_*D_];   // proj_L transposed (R,D)
__device__ __nv_bfloat16 g_LT_lo[(size_t)R_*D_];
__device__ __nv_bfloat16 g_PR_hi[(size_t)R_*D_];   // proj_R (R,D)
__device__ __nv_bfloat16 g_PR_lo[(size_t)R_*D_];
__device__ __nv_bfloat16 g_left_hi[(size_t)B_*S_*R_];
__device__ __nv_bfloat16 g_left_lo[(size_t)B_*S_*R_];
__device__ __nv_bfloat16 g_right_hi[(size_t)B_*S_*R_];
__device__ __nv_bfloat16 g_right_lo[(size_t)B_*S_*R_];

// ---------------- PTX helpers ----------------
__device__ __forceinline__ uint32_t smem_u32(const void* p) {
    uint32_t a;
    asm("{ .reg .u64 t; cvta.to.shared.u64 t, %1; cvt.u32.u64 %0, t; }" : "=r"(a) : "l"(p));
    return a;
}
#define SW128(off) ((off) ^ (((off) >> 3) & 0x70))

__device__ __forceinline__ void cp_async16(uint32_t sdst, const void* gsrc) {
    asm volatile("cp.async.cg.shared.global [%0], [%1], 16;" :: "r"(sdst), "l"(gsrc) : "memory");
}
#define CP_COMMIT() asm volatile("cp.async.commit_group;" ::: "memory")

__device__ __forceinline__ void mbar_init(uint32_t a, uint32_t cnt) {
    asm volatile("mbarrier.init.shared.b64 [%0], %1;" :: "r"(a), "r"(cnt) : "memory");
}
__device__ __forceinline__ void mbar_wait(uint32_t a, uint32_t parity) {
    asm volatile(
        "{\n\t.reg .pred P;\n\t"
        "WL_%=:\n\t"
        "mbarrier.try_wait.parity.acquire.cta.shared::cta.b64 P, [%0], %1, 0x989680;\n\t"
        "@P bra WD_%=;\n\t"
        "bra WL_%=;\n\t"
        "WD_%=:\n\t}"
        :: "r"(a), "r"(parity) : "memory");
}

#if HAS_TCGEN05
__device__ __forceinline__ uint32_t elect_one() {
    uint32_t p;
    asm volatile("{ .reg .pred p; elect.sync _|p, 0xFFFFFFFF; selp.b32 %0,1,0,p; }" : "=r"(p));
    return p;
}

// SW128 K-major SMEM descriptor (layout=2, version=1, SBO=64, LBO=1)
__device__ __forceinline__ uint64_t make_desc(uint32_t addr) {
    const uint64_t base = (uint64_t(2) << 61) | (uint64_t(1) << 46)
                        | (uint64_t(64) << 32) | (uint64_t(1) << 16);
    return base | ((uint64_t)(addr >> 4) & 0x3FFF);
}

__device__ __forceinline__ void mma_bf16_ss(uint32_t d, uint64_t ad, uint64_t bd,
                                            uint32_t idesc, bool acc) {
    uint32_t en = acc ? 1u : 0u, z = 0u;
    asm volatile(
        "{\n\t.reg .pred p;\n\tsetp.ne.u32 p, %5, 0;\n\t"
        "tcgen05.mma.cta_group::1.kind::f16 [%0], %1, %2, %3, {%4,%4,%4,%4}, p;\n\t}"
        :: "r"(d), "l"(ad), "l"(bd), "r"(idesc), "r"(z), "r"(en) : "memory");
}
__device__ __forceinline__ void tc_commit(uint32_t mbar) {
    asm volatile(
        "tcgen05.commit.cta_group::1.mbarrier::arrive::one.shared::cluster.b64 [%0];"
        :: "r"(mbar) : "memory");
}
#endif  // HAS_TCGEN05

// ---------------- conversion kernels ----------------
__device__ __forceinline__ void split1(float v, __nv_bfloat16& h, __nv_bfloat16& l) {
    h = __float2bfloat16_rn(v);
    l = __float2bfloat16_rn(v - __bfloat162float(h));
}

__global__ void split_kernel(const float4* __restrict__ src,
                             __nv_bfloat16* __restrict__ hi,
                             __nv_bfloat16* __restrict__ lo) {
    int i = blockIdx.x * blockDim.x + threadIdx.x;
    float4 v = src[i];
    __nv_bfloat16 h[4], l[4];
    split1(v.x, h[0], l[0]); split1(v.y, h[1], l[1]);
    split1(v.z, h[2], l[2]); split1(v.w, h[3], l[3]);
    *(uint64_t*)(hi + (size_t)i * 4) = *(const uint64_t*)h;
    *(uint64_t*)(lo + (size_t)i * 4) = *(const uint64_t*)l;
}

// proj_L (D,R) -> transposed split (R,D)
__global__ void tsplit_kernel(const float* __restrict__ src,
                              __nv_bfloat16* __restrict__ hi,
                              __nv_bfloat16* __restrict__ lo) {
    __shared__ float t[32][33];
    int tx = threadIdx.x, ty = threadIdx.y;
    int d0 = blockIdx.y * 32, r0 = blockIdx.x * 32;
    t[ty][tx] = src[(size_t)(d0 + ty) * R_ + r0 + tx];
    __syncthreads();
    float v = t[tx][ty];                // out[r0+ty][d0+tx]
    size_t o = (size_t)(r0 + ty) * D_ + d0 + tx;
    __nv_bfloat16 h, l; split1(v, h, l);
    hi[o] = h; lo[o] = l;
}

// ---------------- tcgen05 NT GEMM with 3-term bf16 split ----------------
// One chunk = one K-slice of 64; loads all 4 tiles (Ahi,Alo,Bhi,Blo) once and
// issues all 3 split-term MMA groups into the same TMEM accumulator.
// C[M,N] = Ahi*Bhi^T + Ahi*Blo^T + Alo*Bhi^T ; out fp32(+bias) or bf16 hi/lo.
template <int TN, int ST>
__global__ void __launch_bounds__(256)
tc_gemm(const __nv_bfloat16* __restrict__ A_hi, const __nv_bfloat16* __restrict__ A_lo,
        const __nv_bfloat16* __restrict__ B_hi, const __nv_bfloat16* __restrict__ B_lo,
        float* __restrict__ Cf,
        __nv_bfloat16* __restrict__ Chi, __nv_bfloat16* __restrict__ Clo,
        const float* __restrict__ bias,
        int K, int ldc,
        long strideA, long strideB, long strideC)
{
#if HAS_TCGEN05
    constexpr int A_BYTES = TILE_M * 128;            // one A tile (hi or lo)
    constexpr int B_BYTES = TN * 128;                // one B tile (hi or lo)
    constexpr int STAGE   = 2 * A_BYTES + 2 * B_BYTES;
    constexpr uint32_t IDESC =
        (1u<<4) | (1u<<7) | (1u<<10) | ((TN/8)<<17) | ((TILE_M/16)<<24);

    extern __shared__ char smem_raw[];
    const uint32_t raw = smem_u32(smem_raw);
    const uint32_t tileBase = (raw + 1023u) & ~1023u;
    const uint32_t barBase  = tileBase + ST * STAGE;
    const uint32_t tmemSlot = barBase + 64;

    const int tid = threadIdx.x, wid = tid >> 5, lane = tid & 31;
    const int z  = blockIdx.z;
    const int m0 = blockIdx.y * TILE_M;
    const int n0 = blockIdx.x * TN;

    A_hi += (size_t)z * strideA;  A_lo += (size_t)z * strideA;
    B_hi += (size_t)z * strideB;  B_lo += (size_t)z * strideB;

    const int chunks = K / KCH;

    if (wid == 0) {
        asm volatile("tcgen05.alloc.cta_group::1.sync.aligned.shared::cta.b32 [%0], %1;"
                     :: "r"(tmemSlot), "r"(TN) : "memory");
        asm volatile("tcgen05.relinquish_alloc_permit.cta_group::1.sync.aligned;");
    }
    if (tid == 0) {
#pragma unroll
        for (int s = 0; s < ST; s++) mbar_init(barBase + s * 8, 1);
    }
    __syncthreads();
    uint32_t tmem;
    asm volatile("ld.shared.b32 %0, [%1];" : "=r"(tmem) : "r"(tmemSlot));

    auto load_chunk = [&](int kc, int s) {
        const __nv_bfloat16* ah = A_hi + (size_t)m0 * K + kc * KCH;
        const __nv_bfloat16* al = A_lo + (size_t)m0 * K + kc * KCH;
        const __nv_bfloat16* bh = B_hi + (size_t)n0 * K + kc * KCH;
        const __nv_bfloat16* bl = B_lo + (size_t)n0 * K + kc * KCH;
        const uint32_t sAh = tileBase + s * STAGE;
        const uint32_t sAl = sAh + A_BYTES;
        const uint32_t sBh = sAl + A_BYTES;
        const uint32_t sBl = sBh + B_BYTES;
        // A tiles: TILE_M rows x 8 float4  (1024 cp per tile)
#pragma unroll
        for (int i = 0; i < (TILE_M * 8) / 256; i++) {
            int l = tid + i * 256;
            int row = l >> 3, c16 = l & 7;
            uint32_t off = SW128(row * 128 + c16 * 16);
            size_t go = (size_t)row * K + c16 * 8;
            cp_async16(sAh + off, ah + go);
            cp_async16(sAl + off, al + go);
        }
        // B tiles: TN rows x 8 float4
#pragma unroll
        for (int i = 0; i < (TN * 8) / 256; i++) {
            int l = tid + i * 256;
            int row = l >> 3, c16 = l & 7;
            uint32_t off = SW128(row * 128 + c16 * 16);
            size_t go = (size_t)row * K + c16 * 8;
            cp_async16(sBh + off, bh + go);
            cp_async16(sBl + off, bl + go);
        }
    };

    // prologue: fill ST-1 stages
#pragma unroll
    for (int s = 0; s < ST - 1; s++) { load_chunk(s, s); CP_COMMIT(); }

    for (int c = 0; c < chunks; c++) {
        int cl = c + ST - 1;
        if (cl < chunks) {
            int s = cl % ST, u = cl / ST;
            if (u > 0) mbar_wait(barBase + s * 8, (u - 1) & 1);
            load_chunk(cl, s);
        }
        CP_COMMIT();
        asm volatile("cp.async.wait_group %0;" :: "n"(ST - 1) : "memory");
        asm volatile("fence.proxy.async.shared::cta;" ::: "memory");
        __syncthreads();
        if (wid == 0) {
            if (elect_one()) {
                int s = c % ST;
                uint32_t sAh = tileBase + s * STAGE;
                uint64_t dAh = make_desc(sAh);
                uint64_t dAl = make_desc(sAh + A_BYTES);
                uint64_t dBh = make_desc(sAh + 2 * A_BYTES);
                uint64_t dBl = make_desc(sAh + 2 * A_BYTES + B_BYTES);
                // term 0: Ahi*Bhi, term 1: Ahi*Blo, term 2: Alo*Bhi
#pragma unroll
                for (int km = 0; km < 4; km++)
                    mma_bf16_ss(tmem, dAh + km*2, dBh + km*2, IDESC, !(c == 0 && km == 0));
#pragma unroll
                for (int km = 0; km < 4; km++)
                    mma_bf16_ss(tmem, dAh + km*2, dBl + km*2, IDESC, true);
#pragma unroll
                for (int km = 0; km < 4; km++)
                    mma_bf16_ss(tmem, dAl + km*2, dBh + km*2, IDESC, true);
                tc_commit(barBase + s * 8);
            }
        }
    }

    // wait for last chunk's MMA
    {
        int sl = (chunks - 1) % ST, ul = (chunks - 1) / ST;
        mbar_wait(barBase + sl * 8, ul & 1);
    }
    asm volatile("tcgen05.fence::after_thread_sync;" ::: "memory");

    if (wid < 4) {
        const float bv = bias ? bias[0] : 0.f;
        const int row = m0 + wid * 32 + lane;
#pragma unroll
        for (int pass = 0; pass < TN / 32; pass++) {
            uint32_t r[32];
            asm volatile(
                "tcgen05.ld.sync.aligned.32x32b.x32.b32 "
                "{%0,%1,%2,%3,%4,%5,%6,%7,%8,%9,%10,%11,%12,%13,%14,%15,"
                "%16,%17,%18,%19,%20,%21,%22,%23,%24,%25,%26,%27,%28,%29,%30,%31}, [%32];"
                : "=r"(r[0]), "=r"(r[1]), "=r"(r[2]), "=r"(r[3]), "=r"(r[4]), "=r"(r[5]),
                  "=r"(r[6]), "=r"(r[7]), "=r"(r[8]), "=r"(r[9]), "=r"(r[10]), "=r"(r[11]),
                  "=r"(r[12]), "=r"(r[13]), "=r"(r[14]), "=r"(r[15]), "=r"(r[16]), "=r"(r[17]),
                  "=r"(r[18]), "=r"(r[19]), "=r"(r[20]), "=r"(r[21]), "=r"(r[22]), "=r"(r[23]),
                  "=r"(r[24]), "=r"(r[25]), "=r"(r[26]), "=r"(r[27]), "=r"(r[28]), "=r"(r[29]),
                  "=r"(r[30]), "=r"(r[31])
                : "r"(tmem + pass * 32));
            asm volatile("tcgen05.wait::ld.sync.aligned;" ::: "memory");

            if (Cf) {
                float* dst = Cf + (size_t)z * strideC + (size_t)row * ldc + n0 + pass * 32;
#pragma unroll
                for (int g = 0; g < 8; g++) {
                    float4 v = make_float4(__uint_as_float(r[g*4+0]) + bv,
                                           __uint_as_float(r[g*4+1]) + bv,
                                           __uint_as_float(r[g*4+2]) + bv,
                                           __uint_as_float(r[g*4+3]) + bv);
                    *(float4*)(dst + g * 4) = v;
                }
            } else {
                size_t o = (size_t)row * ldc + n0 + pass * 32;
#pragma unroll
                for (int g = 0; g < 4; g++) {
                    union { __nv_bfloat16 h[8]; uint4 u; } ph, pl;
#pragma unroll
                    for (int e = 0; e < 8; e++) {
                        float v = __uint_as_float(r[g * 8 + e]);
                        split1(v, ph.h[e], pl.h[e]);
                    }
                    *(uint4*)(Chi + o + g * 8) = ph.u;
                    *(uint4*)(Clo + o + g * 8) = pl.u;
                }
            }
        }
    }
    asm volatile("tcgen05.fence::before_thread_sync;" ::: "memory");
    __syncthreads();
    if (wid == 0) {
        asm volatile("tcgen05.dealloc.cta_group::1.sync.aligned.b32 %0, %1;"
                     :: "r"(tmem), "r"(TN) : "memory");
    }
#endif  // HAS_TCGEN05
}

// ---------------- launch ----------------
extern "C" void kernel_launch(void* const* d_in, const int* in_sizes, int n_in,
                              void* d_out, int out_size)
{
    const float* batch  = (const float*)d_in[0];   // (B,S,D)
    const float* proj_L = (const float*)d_in[1];   // (D,R)
    const float* proj_R = (const float*)d_in[2];   // (R,D)
    const float* bias   = (const float*)d_in[3];   // (1,)
    float* out = (float*)d_out;                    // (B,S,S)

    __nv_bfloat16 *batch_hi, *batch_lo, *LT_hi, *LT_lo, *PR_hi, *PR_lo;
    __nv_bfloat16 *left_hi, *left_lo, *right_hi, *right_lo;
    cudaGetSymbolAddress((void**)&batch_hi, g_batch_hi);
    cudaGetSymbolAddress((void**)&batch_lo, g_batch_lo);
    cudaGetSymbolAddress((void**)&LT_hi, g_LT_hi);
    cudaGetSymbolAddress((void**)&LT_lo, g_LT_lo);
    cudaGetSymbolAddress((void**)&PR_hi, g_PR_hi);
    cudaGetSymbolAddress((void**)&PR_lo, g_PR_lo);
    cudaGetSymbolAddress((void**)&left_hi, g_left_hi);
    cudaGetSymbolAddress((void**)&left_lo, g_left_lo);
    cudaGetSymbolAddress((void**)&right_hi, g_right_hi);
    cudaGetSymbolAddress((void**)&right_lo, g_right_lo);

    // smem: stage = 2*16KB (A) + 2*(TN*128) (B)
    constexpr int SMEM_128 = 1024 + 3 * (2*16384 + 2*16384) + 256;   // 3 stages, 64KB each
    constexpr int SMEM_256 = 1024 + 2 * (2*16384 + 2*32768) + 256;   // 2 stages, 96KB each
    cudaFuncSetAttribute(tc_gemm<128,3>, cudaFuncAttributeMaxDynamicSharedMemorySize, SMEM_128);
    cudaFuncSetAttribute(tc_gemm<256,2>, cudaFuncAttributeMaxDynamicSharedMemorySize, SMEM_256);

    // 1) input conversions
    split_kernel<<<(B_*S_*D_/4)/256, 256>>>((const float4*)batch, batch_hi, batch_lo);
    split_kernel<<<(R_*D_/4)/256, 256>>>((const float4*)proj_R, PR_hi, PR_lo);
    tsplit_kernel<<<dim3(R_/32, D_/32), dim3(32, 32)>>>(proj_L, LT_hi, LT_lo);

    // 2) left = batch @ proj_L  (M=8192, N=256, K=1024), emit bf16 split
    tc_gemm<128,3><<<dim3(R_/128, (B_*S_)/TILE_M, 1), 256, SMEM_128>>>(
        batch_hi, batch_lo, LT_hi, LT_lo,
        nullptr, left_hi, left_lo, nullptr,
        D_, R_, 0, 0, 0);

    // 3) right = batch @ proj_R^T (same shape), emit bf16 split
    tc_gemm<128,3><<<dim3(R_/128, (B_*S_)/TILE_M, 1), 256, SMEM_128>>>(
        batch_hi, batch_lo, PR_hi, PR_lo,
        nullptr, right_hi, right_lo, nullptr,
        D_, R_, 0, 0, 0);

    // 4) logits[b] = left[b] @ right[b]^T + bias  (batched, M=1024 N=1024 K=256)
    tc_gemm<256,2><<<dim3(S_/256, S_/TILE_M, B_), 256, SMEM_256>>>(
        left_hi, left_lo, right_hi, right_lo,
        out, nullptr, nullptr, bias,
        R_, S_, (long)S_*R_, (long)S_*R_, (long)S_*S_);
}

// round 8
// speedup vs baseline: 5.8317x; 1.2498x over previous
#include <cuda_runtime.h>
#include <cuda_bf16.h>
#include <cstdint>

// tcgen05 is arch-SPECIFIC (sm_103a): guard device code so the harness's plain
// compute_103 PTX pass compiles. The sm_103a cubin is what actually runs.
#if defined(__CUDA_ARCH__) && (defined(__CUDA_ARCH_FEAT_SM103_ALL) || \
    defined(__CUDA_ARCH_FEAT_SM100_ALL) || defined(__CUDA_ARCH_SPECIFIC__) || \
    defined(__CUDA_ARCH_FAMILY_SPECIFIC__))
#define HAS_TCGEN05 1
#else
#define HAS_TCGEN05 0
#endif

// Problem dims (fixed)
#define B_  8
#define S_  1024
#define D_  1024
#define R_  256

#define TILE_M 128
#define KCH    64          // bf16 K elements per chunk (=128B SW128 row)

// ---------------- scratch (device globals; no allocs allowed) ----------------
__device__ __nv_bfloat16 g_batch_hi[(size_t)B_*S_*D_];
__device__ __nv_bfloat16 g_batch_lo[(size_t)B_*S_*D_];
__device__ __nv_bfloat16 g_LT_hi[(size_t)R_*D_];   // proj_L transposed (R,D)
__device__ __nv_bfloat16 g_LT_lo[(size_t)R_*D_];
__device__ __nv_bfloat16 g_PR_hi[(size_t)R_*D_];   // proj_R (R,D)
__device__ __nv_bfloat16 g_PR_lo[(size_t)R_*D_];
__device__ __nv_bfloat16 g_left_hi[(size_t)B_*S_*R_];
__device__ __nv_bfloat16 g_left_lo[(size_t)B_*S_*R_];
__device__ __nv_bfloat16 g_right_hi[(size_t)B_*S_*R_];
__device__ __nv_bfloat16 g_right_lo[(size_t)B_*S_*R_];

// ---------------- PTX helpers ----------------
__device__ __forceinline__ uint32_t smem_u32(const void* p) {
    uint32_t a;
    asm("{ .reg .u64 t; cvta.to.shared.u64 t, %1; cvt.u32.u64 %0, t; }" : "=r"(a) : "l"(p));
    return a;
}
#define SW128(off) ((off) ^ (((off) >> 3) & 0x70))

__device__ __forceinline__ void cp_async16(uint32_t sdst, const void* gsrc) {
    asm volatile("cp.async.cg.shared.global [%0], [%1], 16;" :: "r"(sdst), "l"(gsrc) : "memory");
}
// .noinc is load-bearing: without it the pend-count is incremented at issue and
// the completion arrive nets to zero against the init count -> deadlock (R6).
__device__ __forceinline__ void cp_async_arrive(uint32_t mbar) {
    asm volatile("cp.async.mbarrier.arrive.noinc.shared.b64 [%0];" :: "r"(mbar) : "memory");
}

__device__ __forceinline__ void mbar_init(uint32_t a, uint32_t cnt) {
    asm volatile("mbarrier.init.shared.b64 [%0], %1;" :: "r"(a), "r"(cnt) : "memory");
}
__device__ __forceinline__ void mbar_wait(uint32_t a, uint32_t parity) {
    asm volatile(
        "{\n\t.reg .pred P;\n\t"
        "WL_%=:\n\t"
        "mbarrier.try_wait.parity.acquire.cta.shared::cta.b64 P, [%0], %1, 0x989680;\n\t"
        "@P bra WD_%=;\n\t"
        "bra WL_%=;\n\t"
        "WD_%=:\n\t}"
        :: "r"(a), "r"(parity) : "memory");
}

#if HAS_TCGEN05
__device__ __forceinline__ uint32_t elect_one() {
    uint32_t p;
    asm volatile("{ .reg .pred p; elect.sync _|p, 0xFFFFFFFF; selp.b32 %0,1,0,p; }" : "=r"(p));
    return p;
}

// SW128 K-major SMEM descriptor (layout=2, version=1, SBO=64, LBO=1)
__device__ __forceinline__ uint64_t make_desc(uint32_t addr) {
    const uint64_t base = (uint64_t(2) << 61) | (uint64_t(1) << 46)
                        | (uint64_t(64) << 32) | (uint64_t(1) << 16);
    return base | ((uint64_t)(addr >> 4) & 0x3FFF);
}

__device__ __forceinline__ void mma_bf16_ss(uint32_t d, uint64_t ad, uint64_t bd,
                                            uint32_t idesc, bool acc) {
    uint32_t en = acc ? 1u : 0u, z = 0u;
    asm volatile(
        "{\n\t.reg .pred p;\n\tsetp.ne.u32 p, %5, 0;\n\t"
        "tcgen05.mma.cta_group::1.kind::f16 [%0], %1, %2, %3, {%4,%4,%4,%4}, p;\n\t}"
        :: "r"(d), "l"(ad), "l"(bd), "r"(idesc), "r"(z), "r"(en) : "memory");
}
__device__ __forceinline__ void tc_commit(uint32_t mbar) {
    asm volatile(
        "tcgen05.commit.cta_group::1.mbarrier::arrive::one.shared::cluster.b64 [%0];"
        :: "r"(mbar) : "memory");
}
#endif  // HAS_TCGEN05

// ---------------- conversion kernels ----------------
__device__ __forceinline__ void split1(float v, __nv_bfloat16& h, __nv_bfloat16& l) {
    h = __float2bfloat16_rn(v);
    l = __float2bfloat16_rn(v - __bfloat162float(h));
}

__global__ void split_kernel(const float4* __restrict__ src,
                             __nv_bfloat16* __restrict__ hi,
                             __nv_bfloat16* __restrict__ lo) {
    int i = blockIdx.x * blockDim.x + threadIdx.x;
    float4 v = src[i];
    __nv_bfloat16 h[4], l[4];
    split1(v.x, h[0], l[0]); split1(v.y, h[1], l[1]);
    split1(v.z, h[2], l[2]); split1(v.w, h[3], l[3]);
    *(uint64_t*)(hi + (size_t)i * 4) = *(const uint64_t*)h;
    *(uint64_t*)(lo + (size_t)i * 4) = *(const uint64_t*)l;
}

// proj_L (D,R) -> transposed split (R,D)
__global__ void tsplit_kernel(const float* __restrict__ src,
                              __nv_bfloat16* __restrict__ hi,
                              __nv_bfloat16* __restrict__ lo) {
    __shared__ float t[32][33];
    int tx = threadIdx.x, ty = threadIdx.y;
    int d0 = blockIdx.y * 32, r0 = blockIdx.x * 32;
    t[ty][tx] = src[(size_t)(d0 + ty) * R_ + r0 + tx];
    __syncthreads();
    float v = t[tx][ty];                // out[r0+ty][d0+tx]
    size_t o = (size_t)(r0 + ty) * D_ + d0 + tx;
    __nv_bfloat16 h, l; split1(v, h, l);
    hi[o] = h; lo[o] = l;
}

// ---------------- warp-specialized tcgen05 NT GEMM, 3-term bf16 split -------
// 288 threads: warps 0-7 = producers (cp.async pipelines), warp 8 = MMA issuer.
// One chunk = K-slice of 64, tiles Ahi|Alo|Bhi|Blo; 3 split terms into one
// TMEM fp32 accumulator: C = Ahi*Bhi^T + Ahi*Blo^T + Alo*Bhi^T.
// zmode==1: grid.z selects (B,C) pair (fused left/right GEMM, shared A).
// zmode==0: grid.z = batch index with strides (batched GEMM3).
template <int TN, int ST>
__global__ void __launch_bounds__(288)
tc_gemm(const __nv_bfloat16* __restrict__ A_hi, const __nv_bfloat16* __restrict__ A_lo,
        const __nv_bfloat16* __restrict__ B0_hi, const __nv_bfloat16* __restrict__ B0_lo,
        const __nv_bfloat16* __restrict__ B1_hi, const __nv_bfloat16* __restrict__ B1_lo,
        float* __restrict__ Cf,
        __nv_bfloat16* __restrict__ C0hi, __nv_bfloat16* __restrict__ C0lo,
        __nv_bfloat16* __restrict__ C1hi, __nv_bfloat16* __restrict__ C1lo,
        const float* __restrict__ bias,
        int K, int ldc,
        long strideA, long strideB, long strideC,
        int zmode)
{
#if HAS_TCGEN05
    constexpr int A_BYTES = TILE_M * 128;            // one A tile (hi or lo)
    constexpr int B_BYTES = TN * 128;                // one B tile (hi or lo)
    constexpr int STAGE   = 2 * A_BYTES + 2 * B_BYTES;
    constexpr uint32_t IDESC =
        (1u<<4) | (1u<<7) | (1u<<10) | ((TN/8)<<17) | ((TILE_M/16)<<24);

    extern __shared__ char smem_raw[];
    const uint32_t raw = smem_u32(smem_raw);
    const uint32_t tileBase = (raw + 1023u) & ~1023u;
    const uint32_t barBase  = tileBase + ST * STAGE;   // full[s]@+16s, empty@+16s+8
    const uint32_t doneBar  = barBase + ST * 16;
    const uint32_t tmemSlot = doneBar + 16;

    const int tid = threadIdx.x, wid = tid >> 5, lane = tid & 31;
    int z = blockIdx.z;
    const int m0 = blockIdx.y * TILE_M;
    const int n0 = blockIdx.x * TN;

    const __nv_bfloat16* B_hi = B0_hi;
    const __nv_bfloat16* B_lo = B0_lo;
    __nv_bfloat16* Chi = C0hi;
    __nv_bfloat16* Clo = C0lo;
    if (zmode == 1) {
        if (z == 1) { B_hi = B1_hi; B_lo = B1_lo; Chi = C1hi; Clo = C1lo; }
        z = 0;
    }
    A_hi += (size_t)z * strideA;  A_lo += (size_t)z * strideA;
    B_hi += (size_t)z * strideB;  B_lo += (size_t)z * strideB;

    const int chunks = K / KCH;

    if (wid == 0) {
        asm volatile("tcgen05.alloc.cta_group::1.sync.aligned.shared::cta.b32 [%0], %1;"
                     :: "r"(tmemSlot), "r"(TN) : "memory");
        asm volatile("tcgen05.relinquish_alloc_permit.cta_group::1.sync.aligned;");
    }
    if (tid == 0) {
#pragma unroll
        for (int s = 0; s < ST; s++) {
            mbar_init(barBase + s * 16, 256);      // full: all producer threads
            mbar_init(barBase + s * 16 + 8, 1);    // empty: one MMA commit
        }
        mbar_init(doneBar, 1);
    }
    __syncthreads();
    uint32_t tmem;
    asm volatile("ld.shared.b32 %0, [%1];" : "=r"(tmem) : "r"(tmemSlot));

    if (tid < 256) {
        // ---------------- producers ----------------
        for (int c = 0; c < chunks; c++) {
            int s = c % ST;
            if (c >= ST) mbar_wait(barBase + s * 16 + 8, (c / ST - 1) & 1);
            const __nv_bfloat16* ah = A_hi + (size_t)m0 * K + c * KCH;
            const __nv_bfloat16* al = A_lo + (size_t)m0 * K + c * KCH;
            const __nv_bfloat16* bh = B_hi + (size_t)n0 * K + c * KCH;
            const __nv_bfloat16* bl = B_lo + (size_t)n0 * K + c * KCH;
            const uint32_t sAh = tileBase + s * STAGE;
            const uint32_t sAl = sAh + A_BYTES;
            const uint32_t sBh = sAl + A_BYTES;
            const uint32_t sBl = sBh + B_BYTES;
#pragma unroll
            for (int i = 0; i < (TILE_M * 8) / 256; i++) {
                int l = tid + i * 256;
                int row = l >> 3, c16 = l & 7;
                uint32_t off = SW128(row * 128 + c16 * 16);
                size_t go = (size_t)row * K + c16 * 8;
                cp_async16(sAh + off, ah + go);
                cp_async16(sAl + off, al + go);
            }
#pragma unroll
            for (int i = 0; i < (TN * 8) / 256; i++) {
                int l = tid + i * 256;
                int row = l >> 3, c16 = l & 7;
                uint32_t off = SW128(row * 128 + c16 * 16);
                size_t go = (size_t)row * K + c16 * 8;
                cp_async16(sBh + off, bh + go);
                cp_async16(sBl + off, bl + go);
            }
            cp_async_arrive(barBase + s * 16);   // arrive full[s] on completion
        }
    } else {
        // ---------------- MMA warp (warp 8) ----------------
        for (int c = 0; c < chunks; c++) {
            int s = c % ST;
            mbar_wait(barBase + s * 16, (c / ST) & 1);
            asm volatile("fence.proxy.async.shared::cta;" ::: "memory");
            if (elect_one()) {
                uint32_t sAh = tileBase + s * STAGE;
                uint64_t dAh = make_desc(sAh);
                uint64_t dAl = make_desc(sAh + A_BYTES);
                uint64_t dBh = make_desc(sAh + 2 * A_BYTES);
                uint64_t dBl = make_desc(sAh + 2 * A_BYTES + B_BYTES);
#pragma unroll
                for (int km = 0; km < 4; km++)
                    mma_bf16_ss(tmem, dAh + km*2, dBh + km*2, IDESC, !(c == 0 && km == 0));
#pragma unroll
                for (int km = 0; km < 4; km++)
                    mma_bf16_ss(tmem, dAh + km*2, dBl + km*2, IDESC, true);
#pragma unroll
                for (int km = 0; km < 4; km++)
                    mma_bf16_ss(tmem, dAl + km*2, dBh + km*2, IDESC, true);
                tc_commit(barBase + s * 16 + 8);
            }
        }
        if (elect_one()) tc_commit(doneBar);   // tracks ALL prior MMAs
    }
    __syncthreads();

    if (wid < 4) {
        mbar_wait(doneBar, 0);
        asm volatile("tcgen05.fence::after_thread_sync;" ::: "memory");
        const float bv = bias ? bias[0] : 0.f;
        const int row = m0 + wid * 32 + lane;
#pragma unroll
        for (int pass = 0; pass < TN / 32; pass++) {
            uint32_t r[32];
            asm volatile(
                "tcgen05.ld.sync.aligned.32x32b.x32.b32 "
                "{%0,%1,%2,%3,%4,%5,%6,%7,%8,%9,%10,%11,%12,%13,%14,%15,"
                "%16,%17,%18,%19,%20,%21,%22,%23,%24,%25,%26,%27,%28,%29,%30,%31}, [%32];"
                : "=r"(r[0]), "=r"(r[1]), "=r"(r[2]), "=r"(r[3]), "=r"(r[4]), "=r"(r[5]),
                  "=r"(r[6]), "=r"(r[7]), "=r"(r[8]), "=r"(r[9]), "=r"(r[10]), "=r"(r[11]),
                  "=r"(r[12]), "=r"(r[13]), "=r"(r[14]), "=r"(r[15]), "=r"(r[16]), "=r"(r[17]),
                  "=r"(r[18]), "=r"(r[19]), "=r"(r[20]), "=r"(r[21]), "=r"(r[22]), "=r"(r[23]),
                  "=r"(r[24]), "=r"(r[25]), "=r"(r[26]), "=r"(r[27]), "=r"(r[28]), "=r"(r[29]),
                  "=r"(r[30]), "=r"(r[31])
                : "r"(tmem + pass * 32));
            asm volatile("tcgen05.wait::ld.sync.aligned;" ::: "memory");

            if (Cf) {
                float* dst = Cf + (size_t)z * strideC + (size_t)row * ldc + n0 + pass * 32;
#pragma unroll
                for (int g = 0; g < 8; g++) {
                    float4 v = make_float4(__uint_as_float(r[g*4+0]) + bv,
                                           __uint_as_float(r[g*4+1]) + bv,
                                           __uint_as_float(r[g*4+2]) + bv,
                                           __uint_as_float(r[g*4+3]) + bv);
                    *(float4*)(dst + g * 4) = v;
                }
            } else {
                size_t o = (size_t)row * ldc + n0 + pass * 32;
#pragma unroll
                for (int g = 0; g < 4; g++) {
                    union { __nv_bfloat16 h[8]; uint4 u; } ph, pl;
#pragma unroll
                    for (int e = 0; e < 8; e++) {
                        float v = __uint_as_float(r[g * 8 + e]);
                        split1(v, ph.h[e], pl.h[e]);
                    }
                    *(uint4*)(Chi + o + g * 8) = ph.u;
                    *(uint4*)(Clo + o + g * 8) = pl.u;
                }
            }
        }
        asm volatile("tcgen05.fence::before_thread_sync;" ::: "memory");
    }
    __syncthreads();
    if (wid == 0) {
        asm volatile("tcgen05.dealloc.cta_group::1.sync.aligned.b32 %0, %1;"
                     :: "r"(tmem), "r"(TN) : "memory");
    }
#endif  // HAS_TCGEN05
}

// ---------------- launch ----------------
extern "C" void kernel_launch(void* const* d_in, const int* in_sizes, int n_in,
                              void* d_out, int out_size)
{
    const float* batch  = (const float*)d_in[0];   // (B,S,D)
    const float* proj_L = (const float*)d_in[1];   // (D,R)
    const float* proj_R = (const float*)d_in[2];   // (R,D)
    const float* bias   = (const float*)d_in[3];   // (1,)
    float* out = (float*)d_out;                    // (B,S,S)

    __nv_bfloat16 *batch_hi, *batch_lo, *LT_hi, *LT_lo, *PR_hi, *PR_lo;
    __nv_bfloat16 *left_hi, *left_lo, *right_hi, *right_lo;
    cudaGetSymbolAddress((void**)&batch_hi, g_batch_hi);
    cudaGetSymbolAddress((void**)&batch_lo, g_batch_lo);
    cudaGetSymbolAddress((void**)&LT_hi, g_LT_hi);
    cudaGetSymbolAddress((void**)&LT_lo, g_LT_lo);
    cudaGetSymbolAddress((void**)&PR_hi, g_PR_hi);
    cudaGetSymbolAddress((void**)&PR_lo, g_PR_lo);
    cudaGetSymbolAddress((void**)&left_hi, g_left_hi);
    cudaGetSymbolAddress((void**)&left_lo, g_left_lo);
    cudaGetSymbolAddress((void**)&right_hi, g_right_hi);
    cudaGetSymbolAddress((void**)&right_lo, g_right_lo);

    // stage = 2*16KB (A) + 2*32KB (B=256 rows) = 96KB; 2 stages
    constexpr int SMEM_256 = 1024 + 2 * (2*16384 + 2*32768) + 256;
    cudaFuncSetAttribute(tc_gemm<256,2>, cudaFuncAttributeMaxDynamicSharedMemorySize, SMEM_256);

    // 1) input conversions
    split_kernel<<<(B_*S_*D_/4)/256, 256>>>((const float4*)batch, batch_hi, batch_lo);
    split_kernel<<<(R_*D_/4)/256, 256>>>((const float4*)proj_R, PR_hi, PR_lo);
    tsplit_kernel<<<dim3(R_/32, D_/32), dim3(32, 32)>>>(proj_L, LT_hi, LT_lo);

    // 2+3) fused: z=0 -> left = batch @ LT^T, z=1 -> right = batch @ PR^T
    //      (M=8192, N=256, K=1024), emit bf16 splits
    tc_gemm<256,2><<<dim3(1, (B_*S_)/TILE_M, 2), 288, SMEM_256>>>(
        batch_hi, batch_lo,
        LT_hi, LT_lo, PR_hi, PR_lo,
        nullptr,
        left_hi, left_lo, right_hi, right_lo,
        nullptr, D_, R_, 0, 0, 0, /*zmode=*/1);

    // 4) logits[b] = left[b] @ right[b]^T + bias  (batched, M=1024 N=1024 K=256)
    tc_gemm<256,2><<<dim3(S_/256, S_/TILE_M, B_), 288, SMEM_256>>>(
        left_hi, left_lo,
        right_hi, right_lo, right_hi, right_lo,
        out,
        nullptr, nullptr, nullptr, nullptr,
        bias, R_, S_, (long)S_*R_, (long)S_*R_, (long)S_*S_, /*zmode=*/0);
}